// round 1
// baseline (speedup 1.0000x reference)
#include <cuda_runtime.h>
#include <cstdint>

// Problem geometry (fixed by the dataset)
#define NTOK  32768          // 8 * 64 * 64 tokens
#define CDIM  512            // channels
#define KCOD  1024           // codebook entries
#define HW    4096           // 64*64 spatial positions per batch

// ---------------- scratch (static device globals; no runtime alloc) --------
__device__ float               g_rnx[NTOK];                    // 1/max(||x_i||,eps)
__device__ float               g_rnm[KCOD];                    // 1/max(||m_j||,eps)
__device__ float               g_rowsum[NTOK];                 // sum_j exp(score)
__device__ unsigned long long  g_amax[NTOK];                   // packed (key, ~idx)
__device__ float               g_exps[33554432];               // exp(score) [NTOK x KCOD], 128MB
__device__ float               g_esum[KCOD * CDIM];            // scatter sums
__device__ float               g_cnt[KCOD];                    // cluster counts (float)
__device__ float               g_newm[KCOD * CDIM];            // EMA-updated codebook

// ---------------- zero the accumulated scratch ------------------------------
__global__ void k_zero() {
    int tid = blockIdx.x * blockDim.x + threadIdx.x;
    int stride = gridDim.x * blockDim.x;
    for (int i = tid; i < NTOK; i += stride) { g_rowsum[i] = 0.f; g_amax[i] = 0ull; }
    for (int i = tid; i < KCOD * CDIM; i += stride) g_esum[i] = 0.f;
    for (int i = tid; i < KCOD; i += stride) g_cnt[i] = 0.f;
}

// ---------------- token norms: 1/max(||x_i||, 1e-12) ------------------------
// block = (32 tokens, 8 channel-lanes); coalesced reads of x[b,c, s..s+31]
__global__ void k_norm_x(const float* __restrict__ x) {
    int i0 = blockIdx.x * 32;
    int b  = i0 >> 12;
    int s0 = i0 & 4095;
    int tx = threadIdx.x;   // token in tile
    int ty = threadIdx.y;   // channel lane
    const float* xb = x + (size_t)b * CDIM * HW + s0 + tx;
    float ss = 0.f;
    for (int c = ty; c < CDIM; c += 8) {
        float v = xb[(size_t)c * HW];
        ss += v * v;
    }
    __shared__ float sm[8][33];
    sm[ty][tx] = ss;
    __syncthreads();
    if (ty == 0) {
        float t = 0.f;
        #pragma unroll
        for (int r = 0; r < 8; r++) t += sm[r][tx];
        g_rnx[i0 + tx] = 1.0f / fmaxf(sqrtf(t), 1e-12f);
    }
}

// ---------------- codebook norms --------------------------------------------
__global__ void k_norm_m(const float* __restrict__ m) {
    int j = blockIdx.x;
    int tid = threadIdx.x;              // 256 threads
    float v0 = m[j * CDIM + tid];
    float v1 = m[j * CDIM + tid + 256];
    float ss = v0 * v0 + v1 * v1;
    #pragma unroll
    for (int o = 16; o > 0; o >>= 1) ss += __shfl_xor_sync(0xffffffffu, ss, o);
    __shared__ float sm[8];
    if ((tid & 31) == 0) sm[tid >> 5] = ss;
    __syncthreads();
    if (tid == 0) {
        float t = 0.f;
        #pragma unroll
        for (int w = 0; w < 8; w++) t += sm[w];
        g_rnm[j] = 1.0f / fmaxf(sqrtf(t), 1e-12f);
    }
}

// ---------------- GEMM1: score = (x_i . m_j) * rnx_i * rnm_j ----------------
// Fused epilogue: write exp(score); atomic per-row sumexp + packed argmax.
// 64x64 tile, 256 threads, 4x4 microtile, k-tile 16. A read directly from x.
__global__ void __launch_bounds__(256) k_gemm1(const float* __restrict__ x,
                                               const float* __restrict__ m) {
    __shared__ float As[16][68];   // [kk][token]
    __shared__ float Bs[16][68];   // [kk][code]
    int tid = threadIdx.x;
    int tx = tid & 15, ty = tid >> 4;
    int i0 = blockIdx.y * 64;      // token tile
    int j0 = blockIdx.x * 64;      // code tile
    int b  = i0 >> 12, s0 = i0 & 4095;
    const float* xb = x + (size_t)b * CDIM * HW + s0;

    float acc[4][4] = {};
    int a_cc = tid >> 4;           // 0..15 (channel within k-tile)
    int a_tg = (tid & 15) * 4;     // token offset (float4)
    int b_j  = tid >> 2;           // 0..63 (code row)
    int b_cg = (tid & 3) * 4;      // channel offset (float4)

    for (int k0 = 0; k0 < CDIM; k0 += 16) {
        float4 av = *(const float4*)(xb + (size_t)(k0 + a_cc) * HW + a_tg);
        float4 bv = *(const float4*)(m + (size_t)(j0 + b_j) * CDIM + k0 + b_cg);
        *(float4*)&As[a_cc][a_tg] = av;
        Bs[b_cg + 0][b_j] = bv.x;
        Bs[b_cg + 1][b_j] = bv.y;
        Bs[b_cg + 2][b_j] = bv.z;
        Bs[b_cg + 3][b_j] = bv.w;
        __syncthreads();
        #pragma unroll
        for (int cc = 0; cc < 16; cc++) {
            float4 a  = *(const float4*)&As[cc][ty * 4];
            float4 bq = *(const float4*)&Bs[cc][tx * 4];
            float ar[4] = {a.x, a.y, a.z, a.w};
            float br[4] = {bq.x, bq.y, bq.z, bq.w};
            #pragma unroll
            for (int u = 0; u < 4; u++)
                #pragma unroll
                for (int v = 0; v < 4; v++)
                    acc[u][v] += ar[u] * br[v];
        }
        __syncthreads();
    }

    // epilogue
    int irow = i0 + ty * 4;
    int jcol = j0 + tx * 4;
    float rx[4], rm[4];
    #pragma unroll
    for (int u = 0; u < 4; u++) rx[u] = g_rnx[irow + u];
    #pragma unroll
    for (int v = 0; v < 4; v++) rm[v] = g_rnm[jcol + v];

    float sums[4];
    unsigned long long packs[4];
    #pragma unroll
    for (int u = 0; u < 4; u++) {
        float rowsum = 0.f;
        float best = -2.0f;     // cosine >= -1
        int bestj = jcol;
        float ev[4];
        #pragma unroll
        for (int v = 0; v < 4; v++) {
            float s = acc[u][v] * rx[u] * rm[v];
            ev[v] = __expf(s);
            rowsum += ev[v];
            if (s > best) { best = s; bestj = jcol + v; }
        }
        float4 evec = make_float4(ev[0], ev[1], ev[2], ev[3]);
        *(float4*)&g_exps[(size_t)(irow + u) * KCOD + jcol] = evec;
        unsigned int bits = __float_as_uint(best);
        unsigned int key  = (bits & 0x80000000u) ? ~bits : (bits | 0x80000000u);
        packs[u] = ((unsigned long long)key << 32)
                 | (unsigned long long)(0xFFFFFFFFu - (unsigned)bestj);
        sums[u] = rowsum;
    }
    // reduce across the 16 tx lanes (same rows)
    #pragma unroll
    for (int o = 1; o < 16; o <<= 1) {
        #pragma unroll
        for (int u = 0; u < 4; u++) {
            sums[u] += __shfl_xor_sync(0xffffffffu, sums[u], o);
            unsigned long long other = __shfl_xor_sync(0xffffffffu, packs[u], o);
            if (other > packs[u]) packs[u] = other;
        }
    }
    if (tx == 0) {
        #pragma unroll
        for (int u = 0; u < 4; u++) {
            atomicAdd(&g_rowsum[irow + u], sums[u]);
            atomicMax(&g_amax[irow + u], packs[u]);
        }
    }
}

// ---------------- scatter: counts + per-cluster raw-x sums ------------------
__global__ void k_scatter(const float* __restrict__ x) {
    int i0 = blockIdx.x * 32;
    int b  = i0 >> 12, s0 = i0 & 4095;
    int tx = threadIdx.x, ty = threadIdx.y;   // 32 x 8
    __shared__ int sidx[32];
    int tid = ty * 32 + tx;
    if (tid < 32) {
        unsigned long long p = g_amax[i0 + tid];
        int idx = (int)(0xFFFFFFFFu - (unsigned)(p & 0xFFFFFFFFull));
        sidx[tid] = idx;
        atomicAdd(&g_cnt[idx], 1.0f);
    }
    __syncthreads();
    int idx = sidx[tx];
    const float* xb = x + (size_t)b * CDIM * HW + s0 + tx;
    float* erow = g_esum + (size_t)idx * CDIM;
    for (int c = ty; c < CDIM; c += 8)
        atomicAdd(&erow[c], xb[(size_t)c * HW]);
}

// ---------------- EMA update of the codebook --------------------------------
__global__ void k_update(const float* __restrict__ m) {
    int kk = blockIdx.x;
    float inv = 0.001f / (g_cnt[kk] + 1e-6f);
    for (int j = threadIdx.x; j < CDIM; j += blockDim.x) {
        g_newm[kk * CDIM + j] = m[kk * CDIM + j] * 0.999f
                              + g_esum[kk * CDIM + j] * inv;
    }
}

// ---------------- GEMM2: out = (exps @ new_m) / rowsum ----------------------
// A = g_exps [N x 1024] row-major, B = g_newm [1024 x 512] row-major.
// Output written directly in [b, c, h, w] layout (float4 along tokens).
__global__ void __launch_bounds__(256) k_gemm2(float* __restrict__ out) {
    __shared__ float As[16][68];   // [kk][token]
    __shared__ float Bs[16][68];   // [kk][channel]
    int tid = threadIdx.x;
    int tx = tid & 15, ty = tid >> 4;
    int i0 = blockIdx.y * 64;      // token tile
    int j0 = blockIdx.x * 64;      // channel tile

    float acc[4][4] = {};
    int a_i  = tid >> 2;           // 0..63 token
    int a_kg = (tid & 3) * 4;      // k offset
    int b_r  = tid >> 4;           // 0..15 k row
    int b_j4 = (tid & 15) * 4;     // channel offset

    for (int k0 = 0; k0 < KCOD; k0 += 16) {
        float4 av = *(const float4*)(g_exps + (size_t)(i0 + a_i) * KCOD + k0 + a_kg);
        float4 bv = *(const float4*)(g_newm + (size_t)(k0 + b_r) * CDIM + j0 + b_j4);
        As[a_kg + 0][a_i] = av.x;
        As[a_kg + 1][a_i] = av.y;
        As[a_kg + 2][a_i] = av.z;
        As[a_kg + 3][a_i] = av.w;
        *(float4*)&Bs[b_r][b_j4] = bv;
        __syncthreads();
        #pragma unroll
        for (int cc = 0; cc < 16; cc++) {
            float4 a  = *(const float4*)&As[cc][ty * 4];
            float4 bq = *(const float4*)&Bs[cc][tx * 4];
            float ar[4] = {a.x, a.y, a.z, a.w};
            float br[4] = {bq.x, bq.y, bq.z, bq.w};
            #pragma unroll
            for (int u = 0; u < 4; u++)
                #pragma unroll
                for (int v = 0; v < 4; v++)
                    acc[u][v] += ar[u] * br[v];
        }
        __syncthreads();
    }

    int b  = i0 >> 12, s0 = i0 & 4095;
    int sbase = s0 + ty * 4;
    float rinv[4];
    #pragma unroll
    for (int u = 0; u < 4; u++) rinv[u] = 1.0f / g_rowsum[i0 + ty * 4 + u];

    #pragma unroll
    for (int v = 0; v < 4; v++) {
        int j = j0 + tx * 4 + v;
        float4 o = make_float4(acc[0][v] * rinv[0], acc[1][v] * rinv[1],
                               acc[2][v] * rinv[2], acc[3][v] * rinv[3]);
        *(float4*)(out + ((size_t)(b * CDIM + j)) * HW + sbase) = o;
    }
}

// ---------------- launch -----------------------------------------------------
extern "C" void kernel_launch(void* const* d_in, const int* in_sizes, int n_in,
                              void* d_out, int out_size) {
    const float* x = (const float*)d_in[0];   // [8, 512, 64, 64]
    const float* m = (const float*)d_in[1];   // [1024, 512]
    float* out = (float*)d_out;               // [8, 512, 64, 64]

    k_zero<<<256, 256>>>();
    k_norm_m<<<KCOD, 256>>>(m);
    k_norm_x<<<NTOK / 32, dim3(32, 8)>>>(x);
    k_gemm1<<<dim3(KCOD / 64, NTOK / 64), 256>>>(x, m);
    k_scatter<<<NTOK / 32, dim3(32, 8)>>>(x);
    k_update<<<KCOD, 256>>>(m);
    k_gemm2<<<dim3(CDIM / 64, NTOK / 64), 256>>>(out);
}

// round 2
// speedup vs baseline: 2.5907x; 2.5907x over previous
#include <cuda_runtime.h>
#include <cstdint>

#define NTOK  32768
#define CDIM  512
#define KCOD  1024
#define HW    4096

// ---------------- scratch ----------------------------------------------------
__device__ float               g_rnx[NTOK];
__device__ float               g_rnm[KCOD];
__device__ float               g_rowsum[NTOK];
__device__ unsigned long long  g_amax[NTOK];
__device__ float               g_exps[33554432];     // [NTOK x KCOD]
__device__ float               g_esum[KCOD * CDIM];
__device__ float               g_cnt[KCOD];
__device__ float               g_newm[KCOD * CDIM];

// ---------------- helpers -----------------------------------------------------
__device__ __forceinline__ float cvt_tf32(float f) {
    uint32_t u;
    asm("cvt.rna.tf32.f32 %0, %1;" : "=r"(u) : "f"(f));
    return __uint_as_float(u);
}

#define MMA_TF32(d, a, b) \
    asm volatile("mma.sync.aligned.m16n8k8.row.col.f32.tf32.tf32.f32 " \
        "{%0,%1,%2,%3}, {%4,%5,%6,%7}, {%8,%9}, {%0,%1,%2,%3};" \
        : "+f"(d[0]), "+f"(d[1]), "+f"(d[2]), "+f"(d[3]) \
        : "r"(a[0]), "r"(a[1]), "r"(a[2]), "r"(a[3]), "r"(b[0]), "r"(b[1]))

__device__ __forceinline__ unsigned long long pack_max(float s, int j) {
    unsigned int bits = __float_as_uint(s);
    unsigned int key  = (bits & 0x80000000u) ? ~bits : (bits | 0x80000000u);
    return ((unsigned long long)key << 32)
         | (unsigned long long)(0xFFFFFFFFu - (unsigned)j);
}

// ---------------- zero --------------------------------------------------------
__global__ void k_zero() {
    int tid = blockIdx.x * blockDim.x + threadIdx.x;
    int stride = gridDim.x * blockDim.x;
    for (int i = tid; i < NTOK; i += stride) { g_rowsum[i] = 0.f; g_amax[i] = 0ull; }
    for (int i = tid; i < KCOD * CDIM; i += stride) g_esum[i] = 0.f;
    for (int i = tid; i < KCOD; i += stride) g_cnt[i] = 0.f;
}

// ---------------- token norms ---------------------------------------------------
__global__ void k_norm_x(const float* __restrict__ x) {
    int i0 = blockIdx.x * 32;
    int b  = i0 >> 12;
    int s0 = i0 & 4095;
    int tx = threadIdx.x, ty = threadIdx.y;
    const float* xb = x + (size_t)b * CDIM * HW + s0 + tx;
    float ss = 0.f;
    for (int c = ty; c < CDIM; c += 8) {
        float v = xb[(size_t)c * HW];
        ss += v * v;
    }
    __shared__ float sm[8][33];
    sm[ty][tx] = ss;
    __syncthreads();
    if (ty == 0) {
        float t = 0.f;
        #pragma unroll
        for (int r = 0; r < 8; r++) t += sm[r][tx];
        g_rnx[i0 + tx] = 1.0f / fmaxf(sqrtf(t), 1e-12f);
    }
}

// ---------------- codebook norms -----------------------------------------------
__global__ void k_norm_m(const float* __restrict__ m) {
    int j = blockIdx.x;
    int tid = threadIdx.x;
    float v0 = m[j * CDIM + tid];
    float v1 = m[j * CDIM + tid + 256];
    float ss = v0 * v0 + v1 * v1;
    #pragma unroll
    for (int o = 16; o > 0; o >>= 1) ss += __shfl_xor_sync(0xffffffffu, ss, o);
    __shared__ float sm[8];
    if ((tid & 31) == 0) sm[tid >> 5] = ss;
    __syncthreads();
    if (tid == 0) {
        float t = 0.f;
        #pragma unroll
        for (int w = 0; w < 8; w++) t += sm[w];
        g_rnm[j] = 1.0f / fmaxf(sqrtf(t), 1e-12f);
    }
}

// ---------------- GEMM1 (tf32 mma): exp(score) + fused rowsum/argmax -----------
// block tile 128 tokens x 128 codes, 8 warps (2m x 4n), warp tile 64x32, ktile 32
__global__ void __launch_bounds__(256) k_gemm1(const float* __restrict__ x,
                                               const float* __restrict__ m) {
    __shared__ float As[32][136];   // [k][token] tf32
    __shared__ float Bs[32][136];   // [k][code]  tf32
    int tid  = threadIdx.x;
    int lane = tid & 31, warp = tid >> 5;
    int g = lane >> 2, tg = lane & 3;
    int wm = warp >> 2, wn = warp & 3;
    int i0 = blockIdx.y * 128;
    int j0 = blockIdx.x * 128;
    int b  = i0 >> 12, s0 = i0 & 4095;
    const float* xb = x + (size_t)b * CDIM * HW + s0;

    float acc[4][4][4] = {};

    int la_c = tid >> 3;           // A: channel row 0..31
    int la_t = (tid & 7) * 4;      // A: token float4 base
    int lb_j = tid >> 1;           // B: code row 0..127
    int lb_c = (tid & 1) * 16;     // B: channel base

    for (int k0 = 0; k0 < CDIM; k0 += 32) {
        #pragma unroll
        for (int q = 0; q < 4; q++) {
            float4 v = *(const float4*)(xb + (size_t)(k0 + la_c) * HW + la_t + 32 * q);
            v.x = cvt_tf32(v.x); v.y = cvt_tf32(v.y);
            v.z = cvt_tf32(v.z); v.w = cvt_tf32(v.w);
            *(float4*)&As[la_c][la_t + 32 * q] = v;
        }
        #pragma unroll
        for (int q = 0; q < 4; q++) {
            float4 v = *(const float4*)(m + (size_t)(j0 + lb_j) * CDIM + k0 + lb_c + 4 * q);
            Bs[lb_c + 4 * q + 0][lb_j] = cvt_tf32(v.x);
            Bs[lb_c + 4 * q + 1][lb_j] = cvt_tf32(v.y);
            Bs[lb_c + 4 * q + 2][lb_j] = cvt_tf32(v.z);
            Bs[lb_c + 4 * q + 3][lb_j] = cvt_tf32(v.w);
        }
        __syncthreads();
        #pragma unroll
        for (int kk = 0; kk < 32; kk += 8) {
            uint32_t af[4][4], bf[4][2];
            #pragma unroll
            for (int mt = 0; mt < 4; mt++) {
                int r = wm * 64 + mt * 16 + g;
                af[mt][0] = __float_as_uint(As[kk + tg    ][r    ]);
                af[mt][1] = __float_as_uint(As[kk + tg    ][r + 8]);
                af[mt][2] = __float_as_uint(As[kk + tg + 4][r    ]);
                af[mt][3] = __float_as_uint(As[kk + tg + 4][r + 8]);
            }
            #pragma unroll
            for (int nt = 0; nt < 4; nt++) {
                int c = wn * 32 + nt * 8 + g;
                bf[nt][0] = __float_as_uint(Bs[kk + tg    ][c]);
                bf[nt][1] = __float_as_uint(Bs[kk + tg + 4][c]);
            }
            #pragma unroll
            for (int mt = 0; mt < 4; mt++)
                #pragma unroll
                for (int nt = 0; nt < 4; nt++)
                    MMA_TF32(acc[mt][nt], af[mt], bf[nt]);
        }
        __syncthreads();
    }

    // fused epilogue: scale -> exp -> store; rowsum + argmax reductions
    int rbase = i0 + wm * 64;
    int cbase = j0 + wn * 32 + 2 * tg;
    float rm0[4], rm1[4];
    #pragma unroll
    for (int nt = 0; nt < 4; nt++) {
        rm0[nt] = g_rnm[cbase + nt * 8];
        rm1[nt] = g_rnm[cbase + nt * 8 + 1];
    }
    #pragma unroll
    for (int mt = 0; mt < 4; mt++) {
        int r0 = rbase + mt * 16 + g;
        int r1 = r0 + 8;
        float rx0 = g_rnx[r0], rx1 = g_rnx[r1];
        float sum0 = 0.f, sum1 = 0.f;
        float best0 = -2.f, best1 = -2.f;
        int bj0 = cbase, bj1 = cbase;
        #pragma unroll
        for (int nt = 0; nt < 4; nt++) {
            int c = cbase + nt * 8;
            float s00 = acc[mt][nt][0] * rx0 * rm0[nt];
            float s01 = acc[mt][nt][1] * rx0 * rm1[nt];
            float s10 = acc[mt][nt][2] * rx1 * rm0[nt];
            float s11 = acc[mt][nt][3] * rx1 * rm1[nt];
            float e00 = __expf(s00), e01 = __expf(s01);
            float e10 = __expf(s10), e11 = __expf(s11);
            *(float2*)&g_exps[(size_t)r0 * KCOD + c] = make_float2(e00, e01);
            *(float2*)&g_exps[(size_t)r1 * KCOD + c] = make_float2(e10, e11);
            sum0 += e00 + e01; sum1 += e10 + e11;
            if (s00 > best0) { best0 = s00; bj0 = c; }
            if (s01 > best0) { best0 = s01; bj0 = c + 1; }
            if (s10 > best1) { best1 = s10; bj1 = c; }
            if (s11 > best1) { best1 = s11; bj1 = c + 1; }
        }
        unsigned long long p0 = pack_max(best0, bj0);
        unsigned long long p1 = pack_max(best1, bj1);
        #pragma unroll
        for (int o = 1; o < 4; o <<= 1) {
            sum0 += __shfl_xor_sync(0xffffffffu, sum0, o);
            sum1 += __shfl_xor_sync(0xffffffffu, sum1, o);
            unsigned long long q0 = __shfl_xor_sync(0xffffffffu, p0, o);
            unsigned long long q1 = __shfl_xor_sync(0xffffffffu, p1, o);
            if (q0 > p0) p0 = q0;
            if (q1 > p1) p1 = q1;
        }
        if (tg == 0) {
            atomicAdd(&g_rowsum[r0], sum0);
            atomicAdd(&g_rowsum[r1], sum1);
            atomicMax(&g_amax[r0], p0);
            atomicMax(&g_amax[r1], p1);
        }
    }
}

// ---------------- scatter ------------------------------------------------------
__global__ void k_scatter(const float* __restrict__ x) {
    int i0 = blockIdx.x * 32;
    int b  = i0 >> 12, s0 = i0 & 4095;
    int tx = threadIdx.x, ty = threadIdx.y;
    __shared__ int sidx[32];
    int tid = ty * 32 + tx;
    if (tid < 32) {
        unsigned long long p = g_amax[i0 + tid];
        int idx = (int)(0xFFFFFFFFu - (unsigned)(p & 0xFFFFFFFFull));
        sidx[tid] = idx;
        atomicAdd(&g_cnt[idx], 1.0f);
    }
    __syncthreads();
    int idx = sidx[tx];
    const float* xb = x + (size_t)b * CDIM * HW + s0 + tx;
    float* erow = g_esum + (size_t)idx * CDIM;
    for (int c = ty; c < CDIM; c += 8)
        atomicAdd(&erow[c], xb[(size_t)c * HW]);
}

// ---------------- EMA update ---------------------------------------------------
__global__ void k_update(const float* __restrict__ m) {
    int kk = blockIdx.x;
    float inv = 0.001f / (g_cnt[kk] + 1e-6f);
    for (int j = threadIdx.x; j < CDIM; j += blockDim.x) {
        g_newm[kk * CDIM + j] = m[kk * CDIM + j] * 0.999f
                              + g_esum[kk * CDIM + j] * inv;
    }
}

// ---------------- GEMM2 (tf32 mma): out = (exps @ new_m) / rowsum --------------
// block tile 128 tokens x 128 channels, ktile 32 over KCOD=1024
__global__ void __launch_bounds__(256) k_gemm2(float* __restrict__ out) {
    __shared__ float As[32][136];   // [k][token]
    __shared__ float Bs[32][136];   // [k][channel]
    int tid  = threadIdx.x;
    int lane = tid & 31, warp = tid >> 5;
    int g = lane >> 2, tg = lane & 3;
    int wm = warp >> 2, wn = warp & 3;
    int i0 = blockIdx.y * 128;
    int j0 = blockIdx.x * 128;

    float acc[4][4][4] = {};

    int la_r = tid >> 1;          // token row 0..127
    int la_k = (tid & 1) * 16;    // k base
    int lb_k = tid >> 3;          // k row 0..31
    int lb_n = (tid & 7) * 4;     // channel float4 base

    for (int k0 = 0; k0 < KCOD; k0 += 32) {
        #pragma unroll
        for (int q = 0; q < 4; q++) {
            float4 v = *(const float4*)(g_exps + (size_t)(i0 + la_r) * KCOD + k0 + la_k + 4 * q);
            As[la_k + 4 * q + 0][la_r] = cvt_tf32(v.x);
            As[la_k + 4 * q + 1][la_r] = cvt_tf32(v.y);
            As[la_k + 4 * q + 2][la_r] = cvt_tf32(v.z);
            As[la_k + 4 * q + 3][la_r] = cvt_tf32(v.w);
        }
        #pragma unroll
        for (int q = 0; q < 4; q++) {
            float4 v = *(const float4*)(g_newm + (size_t)(k0 + lb_k) * CDIM + j0 + lb_n + 32 * q);
            v.x = cvt_tf32(v.x); v.y = cvt_tf32(v.y);
            v.z = cvt_tf32(v.z); v.w = cvt_tf32(v.w);
            *(float4*)&Bs[lb_k][lb_n + 32 * q] = v;
        }
        __syncthreads();
        #pragma unroll
        for (int kk = 0; kk < 32; kk += 8) {
            uint32_t af[4][4], bf[4][2];
            #pragma unroll
            for (int mt = 0; mt < 4; mt++) {
                int r = wm * 64 + mt * 16 + g;
                af[mt][0] = __float_as_uint(As[kk + tg    ][r    ]);
                af[mt][1] = __float_as_uint(As[kk + tg    ][r + 8]);
                af[mt][2] = __float_as_uint(As[kk + tg + 4][r    ]);
                af[mt][3] = __float_as_uint(As[kk + tg + 4][r + 8]);
            }
            #pragma unroll
            for (int nt = 0; nt < 4; nt++) {
                int c = wn * 32 + nt * 8 + g;
                bf[nt][0] = __float_as_uint(Bs[kk + tg    ][c]);
                bf[nt][1] = __float_as_uint(Bs[kk + tg + 4][c]);
            }
            #pragma unroll
            for (int mt = 0; mt < 4; mt++)
                #pragma unroll
                for (int nt = 0; nt < 4; nt++)
                    MMA_TF32(acc[mt][nt], af[mt], bf[nt]);
        }
        __syncthreads();
    }

    int b  = i0 >> 12;
    int rbase = i0 + wm * 64;
    int cbase = j0 + wn * 32 + 2 * tg;
    #pragma unroll
    for (int mt = 0; mt < 4; mt++) {
        int r0 = rbase + mt * 16 + g;
        int r1 = r0 + 8;
        float ri0 = 1.0f / g_rowsum[r0];
        float ri1 = 1.0f / g_rowsum[r1];
        int sA = r0 & 4095, sB = r1 & 4095;
        #pragma unroll
        for (int nt = 0; nt < 4; nt++) {
            int c = cbase + nt * 8;
            out[(size_t)(b * CDIM + c    ) * HW + sA] = acc[mt][nt][0] * ri0;
            out[(size_t)(b * CDIM + c + 1) * HW + sA] = acc[mt][nt][1] * ri0;
            out[(size_t)(b * CDIM + c    ) * HW + sB] = acc[mt][nt][2] * ri1;
            out[(size_t)(b * CDIM + c + 1) * HW + sB] = acc[mt][nt][3] * ri1;
        }
    }
}

// ---------------- launch ---------------------------------------------------------
extern "C" void kernel_launch(void* const* d_in, const int* in_sizes, int n_in,
                              void* d_out, int out_size) {
    const float* x = (const float*)d_in[0];
    const float* m = (const float*)d_in[1];
    float* out = (float*)d_out;

    k_zero<<<256, 256>>>();
    k_norm_m<<<KCOD, 256>>>(m);
    k_norm_x<<<NTOK / 32, dim3(32, 8)>>>(x);
    k_gemm1<<<dim3(KCOD / 128, NTOK / 128), 256>>>(x, m);
    k_scatter<<<NTOK / 32, dim3(32, 8)>>>(x);
    k_update<<<KCOD, 256>>>(m);
    k_gemm2<<<dim3(CDIM / 128, NTOK / 128), 256>>>(out);
}

// round 4
// speedup vs baseline: 3.3122x; 1.2785x over previous
#include <cuda_runtime.h>
#include <cstdint>

#define NTOK  32768
#define CDIM  512
#define KCOD  1024
#define HW    4096

// ---------------- scratch ----------------------------------------------------
__device__ float               g_rnx[NTOK];
__device__ float               g_rnm[KCOD];
__device__ float               g_rowsum[NTOK];
__device__ unsigned long long  g_amax[NTOK];
__device__ float               g_xtf[NTOK * CDIM];            // tf32(x), layout [b][c][s]
__device__ float               g_mtfT[CDIM * KCOD];           // tf32(m), layout [c][j]
__device__ float               g_expsT[(size_t)KCOD * NTOK];  // tf32(exp(score)), [j][token]
__device__ float               g_esum[KCOD * CDIM];
__device__ float               g_cnt[KCOD];
__device__ float               g_newm[KCOD * CDIM];           // tf32(EMA codebook), [k][c]

// ---------------- helpers -----------------------------------------------------
__device__ __forceinline__ float cvt_tf32(float f) {
    uint32_t u;
    asm("cvt.rna.tf32.f32 %0, %1;" : "=r"(u) : "f"(f));
    return __uint_as_float(u);
}

__device__ __forceinline__ void cp16(void* dst, const void* src) {
    unsigned d = (unsigned)__cvta_generic_to_shared(dst);
    asm volatile("cp.async.cg.shared.global [%0], [%1], 16;" :: "r"(d), "l"(src));
}

#define MMA_TF32(d, a, b) \
    asm volatile("mma.sync.aligned.m16n8k8.row.col.f32.tf32.tf32.f32 " \
        "{%0,%1,%2,%3}, {%4,%5,%6,%7}, {%8,%9}, {%0,%1,%2,%3};" \
        : "+f"(d[0]), "+f"(d[1]), "+f"(d[2]), "+f"(d[3]) \
        : "r"(a[0]), "r"(a[1]), "r"(a[2]), "r"(a[3]), "r"(b[0]), "r"(b[1]))

__device__ __forceinline__ unsigned long long pack_max(float s, int j) {
    unsigned int bits = __float_as_uint(s);
    unsigned int key  = (bits & 0x80000000u) ? ~bits : (bits | 0x80000000u);
    return ((unsigned long long)key << 32)
         | (unsigned long long)(0xFFFFFFFFu - (unsigned)j);
}

// ---------------- zero ---------------------------------------------------------
__global__ void k_zero() {
    int tid = blockIdx.x * blockDim.x + threadIdx.x;
    int stride = gridDim.x * blockDim.x;
    for (int i = tid; i < NTOK; i += stride) { g_rowsum[i] = 0.f; g_amax[i] = 0ull; }
    for (int i = tid; i < KCOD * CDIM; i += stride) g_esum[i] = 0.f;
    for (int i = tid; i < KCOD; i += stride) g_cnt[i] = 0.f;
}

// ---------------- token norms ----------------------------------------------------
__global__ void k_norm_x(const float* __restrict__ x) {
    int i0 = blockIdx.x * 32;
    int b  = i0 >> 12;
    int s0 = i0 & 4095;
    int tx = threadIdx.x, ty = threadIdx.y;
    const float* xb = x + (size_t)b * CDIM * HW + s0 + tx;
    float ss = 0.f;
    for (int c = ty; c < CDIM; c += 8) {
        float v = xb[(size_t)c * HW];
        ss += v * v;
    }
    __shared__ float sm[8][33];
    sm[ty][tx] = ss;
    __syncthreads();
    if (ty == 0) {
        float t = 0.f;
        #pragma unroll
        for (int r = 0; r < 8; r++) t += sm[r][tx];
        g_rnx[i0 + tx] = 1.0f / fmaxf(sqrtf(t), 1e-12f);
    }
}

// ---------------- tf32-round x (NO scaling; scale applied in GEMM1 epilogue) ----
__global__ void k_cvt_x(const float* __restrict__ x) {
    size_t f = ((size_t)blockIdx.x * 256 + threadIdx.x) * 4;
    float4 v = *(const float4*)(x + f);
    v.x = cvt_tf32(v.x);
    v.y = cvt_tf32(v.y);
    v.z = cvt_tf32(v.z);
    v.w = cvt_tf32(v.w);
    *(float4*)(g_xtf + f) = v;
}

// ---------------- codebook: norm + transpose + tf32 (NO scaling) ----------------
__global__ void k_prep_m(const float* __restrict__ m) {
    int j = blockIdx.x;
    int tid = threadIdx.x;
    float v0 = m[j * CDIM + tid];
    float v1 = m[j * CDIM + tid + 256];
    float ss = v0 * v0 + v1 * v1;
    #pragma unroll
    for (int o = 16; o > 0; o >>= 1) ss += __shfl_xor_sync(0xffffffffu, ss, o);
    __shared__ float sm[8];
    if ((tid & 31) == 0) sm[tid >> 5] = ss;
    __syncthreads();
    if (tid == 0) {
        float t = 0.f;
        #pragma unroll
        for (int w = 0; w < 8; w++) t += sm[w];
        g_rnm[j] = 1.0f / fmaxf(sqrtf(t), 1e-12f);
    }
    g_mtfT[(size_t)tid * KCOD + j]         = cvt_tf32(v0);
    g_mtfT[(size_t)(tid + 256) * KCOD + j] = cvt_tf32(v1);
}

// ---------------- GEMM1: exp(score) + fused rowsum/argmax ------------------------
// 128x128 tile, 8 warps (2m x 4n), ktile 32, 3-stage cp.async pipeline.
__global__ void __launch_bounds__(256, 2) k_gemm1() {
    extern __shared__ float smem[];   // 3 stages x (As 32x136 + Bs 32x136)
    int tid  = threadIdx.x;
    int lane = tid & 31, warp = tid >> 5;
    int g = lane >> 2, tg = lane & 3;
    int wm = warp >> 2, wn = warp & 3;
    int i0 = blockIdx.y * 128;
    int j0 = blockIdx.x * 128;
    int b  = i0 >> 12, s0 = i0 & 4095;
    const float* Ag = g_xtf + (size_t)b * CDIM * HW + s0;
    const float* Bg = g_mtfT + j0;

    int lrow = tid >> 3;            // 0..31
    int lcol = (tid & 7) * 4;       // 0..28

    float acc[4][4][4] = {};
    const int NIT = CDIM / 32;      // 16

    auto issue = [&](int it) {
        int st = it % 3;
        float* As = smem + st * 8704;
        float* Bs = As + 4352;
        int k0 = it * 32;
        const float* ap = Ag + (size_t)(k0 + lrow) * HW + lcol;
        const float* bp = Bg + (size_t)(k0 + lrow) * KCOD + lcol;
        #pragma unroll
        for (int q = 0; q < 4; q++) {
            cp16(&As[lrow * 136 + lcol + 32 * q], ap + 32 * q);
            cp16(&Bs[lrow * 136 + lcol + 32 * q], bp + 32 * q);
        }
        asm volatile("cp.async.commit_group;");
    };

    issue(0); issue(1);
    for (int it = 0; it < NIT; it++) {
        if (it + 1 < NIT) { asm volatile("cp.async.wait_group 1;"); }
        else              { asm volatile("cp.async.wait_group 0;"); }
        __syncthreads();
        if (it + 2 < NIT) issue(it + 2);
        int st = it % 3;
        const float* As = smem + st * 8704;
        const float* Bs = As + 4352;
        #pragma unroll
        for (int kk = 0; kk < 32; kk += 8) {
            uint32_t af[4][4], bf[4][2];
            #pragma unroll
            for (int mt = 0; mt < 4; mt++) {
                int r = wm * 64 + mt * 16 + g;
                af[mt][0] = __float_as_uint(As[(kk + tg    ) * 136 + r    ]);
                af[mt][1] = __float_as_uint(As[(kk + tg    ) * 136 + r + 8]);
                af[mt][2] = __float_as_uint(As[(kk + tg + 4) * 136 + r    ]);
                af[mt][3] = __float_as_uint(As[(kk + tg + 4) * 136 + r + 8]);
            }
            #pragma unroll
            for (int nt = 0; nt < 4; nt++) {
                int c = wn * 32 + nt * 8 + g;
                bf[nt][0] = __float_as_uint(Bs[(kk + tg    ) * 136 + c]);
                bf[nt][1] = __float_as_uint(Bs[(kk + tg + 4) * 136 + c]);
            }
            #pragma unroll
            for (int mt = 0; mt < 4; mt++)
                #pragma unroll
                for (int nt = 0; nt < 4; nt++)
                    MMA_TF32(acc[mt][nt], af[mt], bf[nt]);
        }
        __syncthreads();
    }

    // epilogue (R2-identical numerics): s = acc*rx*rm in fp32; store tf32(exp);
    // rowsum accumulates UNROUNDED fp32 exps.
    int rbase = i0 + wm * 64;
    int cbase = j0 + wn * 32 + 2 * tg;
    float rm0[4], rm1[4];
    #pragma unroll
    for (int nt = 0; nt < 4; nt++) {
        rm0[nt] = g_rnm[cbase + nt * 8];
        rm1[nt] = g_rnm[cbase + nt * 8 + 1];
    }
    #pragma unroll
    for (int mt = 0; mt < 4; mt++) {
        int r0 = rbase + mt * 16 + g;
        int r1 = r0 + 8;
        float rx0 = g_rnx[r0], rx1 = g_rnx[r1];
        float sum0 = 0.f, sum1 = 0.f;
        float best0 = -2.f, best1 = -2.f;
        int bj0 = cbase, bj1 = cbase;
        #pragma unroll
        for (int nt = 0; nt < 4; nt++) {
            int c = cbase + nt * 8;
            float s00 = acc[mt][nt][0] * rx0 * rm0[nt];
            float s01 = acc[mt][nt][1] * rx0 * rm1[nt];
            float s10 = acc[mt][nt][2] * rx1 * rm0[nt];
            float s11 = acc[mt][nt][3] * rx1 * rm1[nt];
            float e00 = __expf(s00), e01 = __expf(s01);
            float e10 = __expf(s10), e11 = __expf(s11);
            g_expsT[(size_t)c       * NTOK + r0] = cvt_tf32(e00);
            g_expsT[(size_t)(c + 1) * NTOK + r0] = cvt_tf32(e01);
            g_expsT[(size_t)c       * NTOK + r1] = cvt_tf32(e10);
            g_expsT[(size_t)(c + 1) * NTOK + r1] = cvt_tf32(e11);
            sum0 += e00 + e01; sum1 += e10 + e11;
            if (s00 > best0) { best0 = s00; bj0 = c; }
            if (s01 > best0) { best0 = s01; bj0 = c + 1; }
            if (s10 > best1) { best1 = s10; bj1 = c; }
            if (s11 > best1) { best1 = s11; bj1 = c + 1; }
        }
        unsigned long long p0 = pack_max(best0, bj0);
        unsigned long long p1 = pack_max(best1, bj1);
        #pragma unroll
        for (int o = 1; o < 4; o <<= 1) {
            sum0 += __shfl_xor_sync(0xffffffffu, sum0, o);
            sum1 += __shfl_xor_sync(0xffffffffu, sum1, o);
            unsigned long long q0 = __shfl_xor_sync(0xffffffffu, p0, o);
            unsigned long long q1 = __shfl_xor_sync(0xffffffffu, p1, o);
            if (q0 > p0) p0 = q0;
            if (q1 > p1) p1 = q1;
        }
        if (tg == 0) {
            atomicAdd(&g_rowsum[r0], sum0);
            atomicAdd(&g_rowsum[r1], sum1);
            atomicMax(&g_amax[r0], p0);
            atomicMax(&g_amax[r1], p1);
        }
    }
}

// ---------------- scatter --------------------------------------------------------
__global__ void k_scatter(const float* __restrict__ x) {
    int i0 = blockIdx.x * 32;
    int b  = i0 >> 12, s0 = i0 & 4095;
    int tx = threadIdx.x, ty = threadIdx.y;
    __shared__ int sidx[32];
    int tid = ty * 32 + tx;
    if (tid < 32) {
        unsigned long long p = g_amax[i0 + tid];
        int idx = (int)(0xFFFFFFFFu - (unsigned)(p & 0xFFFFFFFFull));
        sidx[tid] = idx;
        atomicAdd(&g_cnt[idx], 1.0f);
    }
    __syncthreads();
    int idx = sidx[tx];
    const float* xb = x + (size_t)b * CDIM * HW + s0 + tx;
    float* erow = g_esum + (size_t)idx * CDIM;
    for (int c = ty; c < CDIM; c += 8)
        atomicAdd(&erow[c], xb[(size_t)c * HW]);
}

// ---------------- EMA update (fp32 math, tf32-rounded at store = R2 load-cvt) -----
__global__ void k_update(const float* __restrict__ m) {
    int kk = blockIdx.x;
    float inv = 0.001f / (g_cnt[kk] + 1e-6f);
    for (int j = threadIdx.x; j < CDIM; j += blockDim.x) {
        g_newm[kk * CDIM + j] = cvt_tf32(m[kk * CDIM + j] * 0.999f
                                       + g_esum[kk * CDIM + j] * inv);
    }
}

// ---------------- GEMM2: out = (expsT^T @ newm) / rowsum --------------------------
__global__ void __launch_bounds__(256, 2) k_gemm2(float* __restrict__ out) {
    extern __shared__ float smem[];
    int tid  = threadIdx.x;
    int lane = tid & 31, warp = tid >> 5;
    int g = lane >> 2, tg = lane & 3;
    int wm = warp >> 2, wn = warp & 3;
    int i0 = blockIdx.y * 128;
    int j0 = blockIdx.x * 128;

    const float* Ag = g_expsT + i0;     // rows: code k, stride NTOK
    const float* Bg = g_newm + j0;      // rows: code k, stride CDIM

    int lrow = tid >> 3;
    int lcol = (tid & 7) * 4;

    float acc[4][4][4] = {};
    const int NIT = KCOD / 32;          // 32

    auto issue = [&](int it) {
        int st = it % 3;
        float* As = smem + st * 8704;
        float* Bs = As + 4352;
        int k0 = it * 32;
        const float* ap = Ag + (size_t)(k0 + lrow) * NTOK + lcol;
        const float* bp = Bg + (size_t)(k0 + lrow) * CDIM + lcol;
        #pragma unroll
        for (int q = 0; q < 4; q++) {
            cp16(&As[lrow * 136 + lcol + 32 * q], ap + 32 * q);
            cp16(&Bs[lrow * 136 + lcol + 32 * q], bp + 32 * q);
        }
        asm volatile("cp.async.commit_group;");
    };

    issue(0); issue(1);
    for (int it = 0; it < NIT; it++) {
        if (it + 1 < NIT) { asm volatile("cp.async.wait_group 1;"); }
        else              { asm volatile("cp.async.wait_group 0;"); }
        __syncthreads();
        if (it + 2 < NIT) issue(it + 2);
        int st = it % 3;
        const float* As = smem + st * 8704;
        const float* Bs = As + 4352;
        #pragma unroll
        for (int kk = 0; kk < 32; kk += 8) {
            uint32_t af[4][4], bf[4][2];
            #pragma unroll
            for (int mt = 0; mt < 4; mt++) {
                int r = wm * 64 + mt * 16 + g;
                af[mt][0] = __float_as_uint(As[(kk + tg    ) * 136 + r    ]);
                af[mt][1] = __float_as_uint(As[(kk + tg    ) * 136 + r + 8]);
                af[mt][2] = __float_as_uint(As[(kk + tg + 4) * 136 + r    ]);
                af[mt][3] = __float_as_uint(As[(kk + tg + 4) * 136 + r + 8]);
            }
            #pragma unroll
            for (int nt = 0; nt < 4; nt++) {
                int c = wn * 32 + nt * 8 + g;
                bf[nt][0] = __float_as_uint(Bs[(kk + tg    ) * 136 + c]);
                bf[nt][1] = __float_as_uint(Bs[(kk + tg + 4) * 136 + c]);
            }
            #pragma unroll
            for (int mt = 0; mt < 4; mt++)
                #pragma unroll
                for (int nt = 0; nt < 4; nt++)
                    MMA_TF32(acc[mt][nt], af[mt], bf[nt]);
        }
        __syncthreads();
    }

    int b = i0 >> 12;
    int rbase = i0 + wm * 64;
    int cbase = j0 + wn * 32 + 2 * tg;
    #pragma unroll
    for (int mt = 0; mt < 4; mt++) {
        int r0 = rbase + mt * 16 + g;
        int r1 = r0 + 8;
        float ri0 = 1.0f / g_rowsum[r0];
        float ri1 = 1.0f / g_rowsum[r1];
        int sA = r0 & 4095, sB = r1 & 4095;
        #pragma unroll
        for (int nt = 0; nt < 4; nt++) {
            int c = cbase + nt * 8;
            out[(size_t)(b * CDIM + c    ) * HW + sA] = acc[mt][nt][0] * ri0;
            out[(size_t)(b * CDIM + c + 1) * HW + sA] = acc[mt][nt][1] * ri0;
            out[(size_t)(b * CDIM + c    ) * HW + sB] = acc[mt][nt][2] * ri1;
            out[(size_t)(b * CDIM + c + 1) * HW + sB] = acc[mt][nt][3] * ri1;
        }
    }
}

// ---------------- launch -----------------------------------------------------------
extern "C" void kernel_launch(void* const* d_in, const int* in_sizes, int n_in,
                              void* d_out, int out_size) {
    const float* x = (const float*)d_in[0];
    const float* m = (const float*)d_in[1];
    float* out = (float*)d_out;

    const int SMEM = 3 * 2 * 32 * 136 * 4;   // 104448 B
    cudaFuncSetAttribute(k_gemm1, cudaFuncAttributeMaxDynamicSharedMemorySize, SMEM);
    cudaFuncSetAttribute(k_gemm2, cudaFuncAttributeMaxDynamicSharedMemorySize, SMEM);

    k_zero<<<256, 256>>>();
    k_norm_x<<<NTOK / 32, dim3(32, 8)>>>(x);
    k_cvt_x<<<(NTOK * CDIM) / (256 * 4), 256>>>(x);
    k_prep_m<<<KCOD, 256>>>(m);
    k_gemm1<<<dim3(KCOD / 128, NTOK / 128), 256, SMEM>>>();
    k_scatter<<<NTOK / 32, dim3(32, 8)>>>(x);
    k_update<<<KCOD, 256>>>(m);
    k_gemm2<<<dim3(CDIM / 128, NTOK / 128), 256, SMEM>>>(out);
}

// round 6
// speedup vs baseline: 4.9030x; 1.4803x over previous
#include <cuda_runtime.h>
#include <cuda_fp16.h>
#include <cstdint>

#define NTOK  32768
#define CDIM  512
#define KCOD  1024
#define HW    4096

// ---------------- scratch ----------------------------------------------------
__device__ float               g_rnx[NTOK];
__device__ float               g_rnm[KCOD];
__device__ float               g_rowsum[NTOK];
__device__ unsigned long long  g_amax[NTOK];
__device__ uint32_t            g_xh[NTOK * CDIM / 2];            // half2(x), [b][c/2][s]
__device__ uint32_t            g_mhT[(CDIM / 2) * KCOD];         // half2(m), [c/2][j]
__device__ uint32_t            g_expsH[(size_t)(KCOD / 2) * NTOK]; // half2(exp), [j/2][token]
__device__ float               g_esum[KCOD * CDIM];
__device__ float               g_cnt[KCOD];
__device__ uint32_t            g_newmH[(KCOD / 2) * CDIM];       // half2(new_m), [k/2][c]

// ---------------- helpers -----------------------------------------------------
__device__ __forceinline__ void cp16(void* dst, const void* src) {
    unsigned d = (unsigned)__cvta_generic_to_shared(dst);
    asm volatile("cp.async.cg.shared.global [%0], [%1], 16;" :: "r"(d), "l"(src));
}

#define MMA_F16(d, a, b) \
    asm volatile("mma.sync.aligned.m16n8k16.row.col.f32.f16.f16.f32 " \
        "{%0,%1,%2,%3}, {%4,%5,%6,%7}, {%8,%9}, {%0,%1,%2,%3};" \
        : "+f"(d[0]), "+f"(d[1]), "+f"(d[2]), "+f"(d[3]) \
        : "r"(a[0]), "r"(a[1]), "r"(a[2]), "r"(a[3]), "r"(b[0]), "r"(b[1]))

__device__ __forceinline__ uint32_t pack_h2(float lo, float hi) {
    __half2 h = __floats2half2_rn(lo, hi);
    return *(uint32_t*)&h;
}

__device__ __forceinline__ unsigned long long pack_max(float s, int j) {
    unsigned int bits = __float_as_uint(s);
    unsigned int key  = (bits & 0x80000000u) ? ~bits : (bits | 0x80000000u);
    return ((unsigned long long)key << 32)
         | (unsigned long long)(0xFFFFFFFFu - (unsigned)j);
}

// ---------------- zero ---------------------------------------------------------
__global__ void k_zero() {
    int tid = blockIdx.x * blockDim.x + threadIdx.x;
    int stride = gridDim.x * blockDim.x;
    for (int i = tid; i < NTOK; i += stride) { g_rowsum[i] = 0.f; g_amax[i] = 0ull; }
    for (int i = tid; i < KCOD * CDIM; i += stride) g_esum[i] = 0.f;
    for (int i = tid; i < KCOD; i += stride) g_cnt[i] = 0.f;
}

// ---------------- token norms ----------------------------------------------------
__global__ void k_norm_x(const float* __restrict__ x) {
    int i0 = blockIdx.x * 32;
    int b  = i0 >> 12;
    int s0 = i0 & 4095;
    int tx = threadIdx.x, ty = threadIdx.y;
    const float* xb = x + (size_t)b * CDIM * HW + s0 + tx;
    float ss = 0.f;
    for (int c = ty; c < CDIM; c += 8) {
        float v = xb[(size_t)c * HW];
        ss += v * v;
    }
    __shared__ float sm[8][33];
    sm[ty][tx] = ss;
    __syncthreads();
    if (ty == 0) {
        float t = 0.f;
        #pragma unroll
        for (int r = 0; r < 8; r++) t += sm[r][tx];
        g_rnx[i0 + tx] = 1.0f / fmaxf(sqrtf(t), 1e-12f);
    }
}

// ---------------- pack x -> half2 along channel pairs, [b][c/2][s] ---------------
__global__ void k_pack_x(const float* __restrict__ x) {
    size_t gid = (size_t)blockIdx.x * 256 + threadIdx.x;
    size_t f = gid * 4;                     // u32 index into g_xh
    int s  = (int)(f & 4095);
    int c2 = (int)((f >> 12) & 255);
    int b  = (int)(f >> 20);
    const float* p0 = x + ((size_t)b * CDIM + 2 * c2) * HW + s;
    float4 v0 = *(const float4*)p0;
    float4 v1 = *(const float4*)(p0 + HW);
    uint4 o;
    o.x = pack_h2(v0.x, v1.x);
    o.y = pack_h2(v0.y, v1.y);
    o.z = pack_h2(v0.z, v1.z);
    o.w = pack_h2(v0.w, v1.w);
    *(uint4*)(g_xh + f) = o;
}

// ---------------- codebook: norm + half2 transpose -------------------------------
__global__ void k_prep_m(const float* __restrict__ m) {
    int j = blockIdx.x;
    int t = threadIdx.x;                   // 256 threads, channel pair each
    float v0 = m[j * CDIM + 2 * t];
    float v1 = m[j * CDIM + 2 * t + 1];
    float ss = v0 * v0 + v1 * v1;
    #pragma unroll
    for (int o = 16; o > 0; o >>= 1) ss += __shfl_xor_sync(0xffffffffu, ss, o);
    __shared__ float sm[8];
    if ((t & 31) == 0) sm[t >> 5] = ss;
    __syncthreads();
    if (t == 0) {
        float tt = 0.f;
        #pragma unroll
        for (int w = 0; w < 8; w++) tt += sm[w];
        g_rnm[j] = 1.0f / fmaxf(sqrtf(tt), 1e-12f);
    }
    g_mhT[(size_t)t * KCOD + j] = pack_h2(v0, v1);
}

// ---------------- tile loader: 16 k-pair rows x 128 u32 cols ---------------------
__device__ __forceinline__ void load_tile16(uint32_t* dst, const uint32_t* src,
                                            int rstride, int tid) {
    #pragma unroll
    for (int q = 0; q < 2; q++) {
        int ch = tid + q * 256;             // 0..511
        int r = ch >> 5;                    // 0..15
        int c4 = (ch & 31) * 4;             // 0..124
        cp16(&dst[r * 136 + c4], src + (size_t)r * rstride + c4);
    }
}

// ---------------- GEMM1: exp(score) + fused rowsum/argmax (fp16 mma) --------------
// CTA 128 tokens x 128 codes, 8 warps (2m x 4n), warp 64x32, ktile 32 (16 pairs),
// 3-stage cp.async pipeline. Stage = (16x136)*2 u32 = 4352 u32.
__global__ void __launch_bounds__(256, 2) k_gemm1() {
    extern __shared__ uint32_t smem[];
    int tid  = threadIdx.x;
    int lane = tid & 31, warp = tid >> 5;
    int g = lane >> 2, tg = lane & 3;
    int wm = warp >> 2, wn = warp & 3;
    int i0 = blockIdx.y * 128;
    int j0 = blockIdx.x * 128;
    int b  = i0 >> 12, s0 = i0 & 4095;
    const uint32_t* Ag = g_xh + (size_t)b * (CDIM / 2) * HW + s0;   // rows c2, stride HW
    const uint32_t* Bg = g_mhT + j0;                                 // rows c2, stride KCOD

    float acc[4][4][4] = {};
    const int NIT = CDIM / 32;      // 16 (16 pair-rows per iter)

    auto issue = [&](int it) {
        uint32_t* As = smem + (it % 3) * 4352;
        uint32_t* Bs = As + 2176;
        int r0 = it * 16;
        load_tile16(As, Ag + (size_t)r0 * HW,   HW,   tid);
        load_tile16(Bs, Bg + (size_t)r0 * KCOD, KCOD, tid);
        asm volatile("cp.async.commit_group;");
    };

    issue(0); issue(1);
    for (int it = 0; it < NIT; it++) {
        if (it + 1 < NIT) { asm volatile("cp.async.wait_group 1;"); }
        else              { asm volatile("cp.async.wait_group 0;"); }
        __syncthreads();
        if (it + 2 < NIT) issue(it + 2);
        const uint32_t* As = smem + (it % 3) * 4352;
        const uint32_t* Bs = As + 2176;
        #pragma unroll
        for (int kp = 0; kp < 16; kp += 8) {
            uint32_t af[4][4], bf[4][2];
            #pragma unroll
            for (int mt = 0; mt < 4; mt++) {
                int r = wm * 64 + mt * 16 + g;
                af[mt][0] = As[(kp + tg    ) * 136 + r    ];
                af[mt][1] = As[(kp + tg    ) * 136 + r + 8];
                af[mt][2] = As[(kp + tg + 4) * 136 + r    ];
                af[mt][3] = As[(kp + tg + 4) * 136 + r + 8];
            }
            #pragma unroll
            for (int nt = 0; nt < 4; nt++) {
                int c = wn * 32 + nt * 8 + g;
                bf[nt][0] = Bs[(kp + tg    ) * 136 + c];
                bf[nt][1] = Bs[(kp + tg + 4) * 136 + c];
            }
            #pragma unroll
            for (int mt = 0; mt < 4; mt++)
                #pragma unroll
                for (int nt = 0; nt < 4; nt++)
                    MMA_F16(acc[mt][nt], af[mt], bf[nt]);
        }
        __syncthreads();
    }

    // epilogue (validated numerics): s = acc*rx*rm fp32; store half2(exp);
    // rowsum accumulates UNROUNDED fp32 exps.
    int rbase = i0 + wm * 64;
    int cbase = j0 + wn * 32 + 2 * tg;
    float rm0[4], rm1[4];
    #pragma unroll
    for (int nt = 0; nt < 4; nt++) {
        rm0[nt] = g_rnm[cbase + nt * 8];
        rm1[nt] = g_rnm[cbase + nt * 8 + 1];
    }
    #pragma unroll
    for (int mt = 0; mt < 4; mt++) {
        int r0 = rbase + mt * 16 + g;
        int r1 = r0 + 8;
        float rx0 = g_rnx[r0], rx1 = g_rnx[r1];
        float sum0 = 0.f, sum1 = 0.f;
        float best0 = -2.f, best1 = -2.f;
        int bj0 = cbase, bj1 = cbase;
        #pragma unroll
        for (int nt = 0; nt < 4; nt++) {
            int c = cbase + nt * 8;
            float s00 = acc[mt][nt][0] * rx0 * rm0[nt];
            float s01 = acc[mt][nt][1] * rx0 * rm1[nt];
            float s10 = acc[mt][nt][2] * rx1 * rm0[nt];
            float s11 = acc[mt][nt][3] * rx1 * rm1[nt];
            float e00 = __expf(s00), e01 = __expf(s01);
            float e10 = __expf(s10), e11 = __expf(s11);
            size_t cp = (size_t)(c >> 1) * NTOK;
            g_expsH[cp + r0] = pack_h2(e00, e01);
            g_expsH[cp + r1] = pack_h2(e10, e11);
            sum0 += e00 + e01; sum1 += e10 + e11;
            if (s00 > best0) { best0 = s00; bj0 = c; }
            if (s01 > best0) { best0 = s01; bj0 = c + 1; }
            if (s10 > best1) { best1 = s10; bj1 = c; }
            if (s11 > best1) { best1 = s11; bj1 = c + 1; }
        }
        unsigned long long p0 = pack_max(best0, bj0);
        unsigned long long p1 = pack_max(best1, bj1);
        #pragma unroll
        for (int o = 1; o < 4; o <<= 1) {
            sum0 += __shfl_xor_sync(0xffffffffu, sum0, o);
            sum1 += __shfl_xor_sync(0xffffffffu, sum1, o);
            unsigned long long q0 = __shfl_xor_sync(0xffffffffu, p0, o);
            unsigned long long q1 = __shfl_xor_sync(0xffffffffu, p1, o);
            if (q0 > p0) p0 = q0;
            if (q1 > p1) p1 = q1;
        }
        if (tg == 0) {
            atomicAdd(&g_rowsum[r0], sum0);
            atomicAdd(&g_rowsum[r1], sum1);
            atomicMax(&g_amax[r0], p0);
            atomicMax(&g_amax[r1], p1);
        }
    }
}

// ---------------- scatter ---------------------------------------------------------
__global__ void k_scatter(const float* __restrict__ x) {
    int i0 = blockIdx.x * 32;
    int b  = i0 >> 12, s0 = i0 & 4095;
    int tx = threadIdx.x, ty = threadIdx.y;
    __shared__ int sidx[32];
    int tid = ty * 32 + tx;
    if (tid < 32) {
        unsigned long long p = g_amax[i0 + tid];
        int idx = (int)(0xFFFFFFFFu - (unsigned)(p & 0xFFFFFFFFull));
        sidx[tid] = idx;
        atomicAdd(&g_cnt[idx], 1.0f);
    }
    __syncthreads();
    int idx = sidx[tx];
    const float* xb = x + (size_t)b * CDIM * HW + s0 + tx;
    float* erow = g_esum + (size_t)idx * CDIM;
    for (int c = ty; c < CDIM; c += 8)
        atomicAdd(&erow[c], xb[(size_t)c * HW]);
}

// ---------------- EMA update -> half2 pairs along k -------------------------------
__global__ void k_update(const float* __restrict__ m) {
    int kp = blockIdx.x;            // k pair
    int k0 = 2 * kp, k1 = k0 + 1;
    float inv0 = 0.001f / (g_cnt[k0] + 1e-6f);
    float inv1 = 0.001f / (g_cnt[k1] + 1e-6f);
    for (int j = threadIdx.x; j < CDIM; j += blockDim.x) {
        float v0 = m[k0 * CDIM + j] * 0.999f + g_esum[k0 * CDIM + j] * inv0;
        float v1 = m[k1 * CDIM + j] * 0.999f + g_esum[k1 * CDIM + j] * inv1;
        g_newmH[(size_t)kp * CDIM + j] = pack_h2(v0, v1);
    }
}

// ---------------- GEMM2: out = (exps @ new_m) / rowsum (fp16 mma) ------------------
__global__ void __launch_bounds__(256, 2) k_gemm2(float* __restrict__ out) {
    extern __shared__ uint32_t smem[];
    int tid  = threadIdx.x;
    int lane = tid & 31, warp = tid >> 5;
    int g = lane >> 2, tg = lane & 3;
    int wm = warp >> 2, wn = warp & 3;
    int i0 = blockIdx.y * 128;   // tokens
    int j0 = blockIdx.x * 128;   // channels

    const uint32_t* Ag = g_expsH + i0;   // rows j-pair, stride NTOK
    const uint32_t* Bg = g_newmH + j0;   // rows k-pair, stride CDIM

    float acc[4][4][4] = {};
    const int NIT = KCOD / 32;           // 32

    auto issue = [&](int it) {
        uint32_t* As = smem + (it % 3) * 4352;
        uint32_t* Bs = As + 2176;
        int r0 = it * 16;
        load_tile16(As, Ag + (size_t)r0 * NTOK, NTOK, tid);
        load_tile16(Bs, Bg + (size_t)r0 * CDIM, CDIM, tid);
        asm volatile("cp.async.commit_group;");
    };

    issue(0); issue(1);
    for (int it = 0; it < NIT; it++) {
        if (it + 1 < NIT) { asm volatile("cp.async.wait_group 1;"); }
        else              { asm volatile("cp.async.wait_group 0;"); }
        __syncthreads();
        if (it + 2 < NIT) issue(it + 2);
        const uint32_t* As = smem + (it % 3) * 4352;
        const uint32_t* Bs = As + 2176;
        #pragma unroll
        for (int kp = 0; kp < 16; kp += 8) {
            uint32_t af[4][4], bf[4][2];
            #pragma unroll
            for (int mt = 0; mt < 4; mt++) {
                int r = wm * 64 + mt * 16 + g;
                af[mt][0] = As[(kp + tg    ) * 136 + r    ];
                af[mt][1] = As[(kp + tg    ) * 136 + r + 8];
                af[mt][2] = As[(kp + tg + 4) * 136 + r    ];
                af[mt][3] = As[(kp + tg + 4) * 136 + r + 8];
            }
            #pragma unroll
            for (int nt = 0; nt < 4; nt++) {
                int c = wn * 32 + nt * 8 + g;
                bf[nt][0] = Bs[(kp + tg    ) * 136 + c];
                bf[nt][1] = Bs[(kp + tg + 4) * 136 + c];
            }
            #pragma unroll
            for (int mt = 0; mt < 4; mt++)
                #pragma unroll
                for (int nt = 0; nt < 4; nt++)
                    MMA_F16(acc[mt][nt], af[mt], bf[nt]);
        }
        __syncthreads();
    }

    int b = i0 >> 12;
    int rbase = i0 + wm * 64;
    int cbase = j0 + wn * 32 + 2 * tg;
    #pragma unroll
    for (int mt = 0; mt < 4; mt++) {
        int r0 = rbase + mt * 16 + g;
        int r1 = r0 + 8;
        float ri0 = 1.0f / g_rowsum[r0];
        float ri1 = 1.0f / g_rowsum[r1];
        int sA = r0 & 4095, sB = r1 & 4095;
        #pragma unroll
        for (int nt = 0; nt < 4; nt++) {
            int c = cbase + nt * 8;
            out[(size_t)(b * CDIM + c    ) * HW + sA] = acc[mt][nt][0] * ri0;
            out[(size_t)(b * CDIM + c + 1) * HW + sA] = acc[mt][nt][1] * ri0;
            out[(size_t)(b * CDIM + c    ) * HW + sB] = acc[mt][nt][2] * ri1;
            out[(size_t)(b * CDIM + c + 1) * HW + sB] = acc[mt][nt][3] * ri1;
        }
    }
}

// ---------------- launch -------------------------------------------------------------
extern "C" void kernel_launch(void* const* d_in, const int* in_sizes, int n_in,
                              void* d_out, int out_size) {
    const float* x = (const float*)d_in[0];
    const float* m = (const float*)d_in[1];
    float* out = (float*)d_out;

    const int SMEM = 3 * 4352 * 4;   // 52224 B
    cudaFuncSetAttribute(k_gemm1, cudaFuncAttributeMaxDynamicSharedMemorySize, SMEM);
    cudaFuncSetAttribute(k_gemm2, cudaFuncAttributeMaxDynamicSharedMemorySize, SMEM);

    k_zero<<<256, 256>>>();
    k_norm_x<<<NTOK / 32, dim3(32, 8)>>>(x);
    k_pack_x<<<(NTOK * CDIM / 2) / (256 * 4), 256>>>(x);
    k_prep_m<<<KCOD, 256>>>(m);
    k_gemm1<<<dim3(KCOD / 128, NTOK / 128), 256, SMEM>>>();
    k_scatter<<<NTOK / 32, dim3(32, 8)>>>(x);
    k_update<<<KCOD / 2, 256>>>(m);
    k_gemm2<<<dim3(CDIM / 128, NTOK / 128), 256, SMEM>>>(out);
}

// round 7
// speedup vs baseline: 6.4996x; 1.3256x over previous
#include <cuda_runtime.h>
#include <cuda_fp16.h>
#include <cstdint>

#define NTOK  32768
#define CDIM  512
#define KCOD  1024
#define HW    4096

// ---------------- scratch ----------------------------------------------------
__device__ float               g_rnx[NTOK];
__device__ float               g_rnm[KCOD];
__device__ float               g_rowsum[NTOK];
__device__ unsigned long long  g_amax[NTOK];
__device__ uint32_t            g_xh[NTOK * CDIM / 2];            // half2(x), [b][c/2][s]
__device__ uint32_t            g_mhT[(CDIM / 2) * KCOD];         // half2(m), [c/2][j]
__device__ uint32_t            g_expsH[(size_t)(KCOD / 2) * NTOK]; // half2(exp), [j/2][token]
__device__ float               g_esum[KCOD * CDIM];
__device__ float               g_cnt[KCOD];
__device__ uint32_t            g_newmH[(KCOD / 2) * CDIM];       // half2(new_m), [k/2][c]

// ---------------- helpers -----------------------------------------------------
__device__ __forceinline__ void cp16(void* dst, const void* src) {
    unsigned d = (unsigned)__cvta_generic_to_shared(dst);
    asm volatile("cp.async.cg.shared.global [%0], [%1], 16;" :: "r"(d), "l"(src));
}

#define MMA_F16(d, a, b) \
    asm volatile("mma.sync.aligned.m16n8k16.row.col.f32.f16.f16.f32 " \
        "{%0,%1,%2,%3}, {%4,%5,%6,%7}, {%8,%9}, {%0,%1,%2,%3};" \
        : "+f"(d[0]), "+f"(d[1]), "+f"(d[2]), "+f"(d[3]) \
        : "r"(a[0]), "r"(a[1]), "r"(a[2]), "r"(a[3]), "r"(b[0]), "r"(b[1]))

__device__ __forceinline__ uint32_t pack_h2(float lo, float hi) {
    __half2 h = __floats2half2_rn(lo, hi);
    return *(uint32_t*)&h;
}

__device__ __forceinline__ unsigned long long pack_max(float s, int j) {
    unsigned int bits = __float_as_uint(s);
    unsigned int key  = (bits & 0x80000000u) ? ~bits : (bits | 0x80000000u);
    return ((unsigned long long)key << 32)
         | (unsigned long long)(0xFFFFFFFFu - (unsigned)j);
}

// ---------------- zero ---------------------------------------------------------
__global__ void k_zero() {
    int tid = blockIdx.x * blockDim.x + threadIdx.x;
    int stride = gridDim.x * blockDim.x;
    for (int i = tid; i < NTOK; i += stride) { g_rowsum[i] = 0.f; g_amax[i] = 0ull; }
    for (int i = tid; i < KCOD * CDIM; i += stride) g_esum[i] = 0.f;
    for (int i = tid; i < KCOD; i += stride) g_cnt[i] = 0.f;
}

// ---------------- fused: token norms + half2 pack (x read ONCE) ------------------
__global__ void k_norm_pack(const float* __restrict__ x) {
    int i0 = blockIdx.x * 32;
    int b  = i0 >> 12;
    int s0 = i0 & 4095;
    int tx = threadIdx.x, ty = threadIdx.y;   // 32 x 8
    const float* xb = x + (size_t)b * CDIM * HW + s0 + tx;
    uint32_t* xo = g_xh + (size_t)b * (CDIM / 2) * HW + s0 + tx;
    float ss = 0.f;
    for (int p = ty; p < CDIM / 2; p += 8) {
        float v0 = xb[(size_t)(2 * p)     * HW];
        float v1 = xb[(size_t)(2 * p + 1) * HW];
        ss += v0 * v0 + v1 * v1;
        xo[(size_t)p * HW] = pack_h2(v0, v1);
    }
    __shared__ float sm[8][33];
    sm[ty][tx] = ss;
    __syncthreads();
    if (ty == 0) {
        float t = 0.f;
        #pragma unroll
        for (int r = 0; r < 8; r++) t += sm[r][tx];
        g_rnx[i0 + tx] = 1.0f / fmaxf(sqrtf(t), 1e-12f);
    }
}

// ---------------- codebook: norm + half2 transpose -------------------------------
__global__ void k_prep_m(const float* __restrict__ m) {
    int j = blockIdx.x;
    int t = threadIdx.x;                   // 256 threads, channel pair each
    float v0 = m[j * CDIM + 2 * t];
    float v1 = m[j * CDIM + 2 * t + 1];
    float ss = v0 * v0 + v1 * v1;
    #pragma unroll
    for (int o = 16; o > 0; o >>= 1) ss += __shfl_xor_sync(0xffffffffu, ss, o);
    __shared__ float sm[8];
    if ((t & 31) == 0) sm[t >> 5] = ss;
    __syncthreads();
    if (t == 0) {
        float tt = 0.f;
        #pragma unroll
        for (int w = 0; w < 8; w++) tt += sm[w];
        g_rnm[j] = 1.0f / fmaxf(sqrtf(tt), 1e-12f);
    }
    g_mhT[(size_t)t * KCOD + j] = pack_h2(v0, v1);
}

// ---------------- tile loader: 16 k-pair rows x 128 u32 cols ---------------------
__device__ __forceinline__ void load_tile16(uint32_t* dst, const uint32_t* src,
                                            int rstride, int tid) {
    #pragma unroll
    for (int q = 0; q < 2; q++) {
        int ch = tid + q * 256;             // 0..511
        int r = ch >> 5;                    // 0..15
        int c4 = (ch & 31) * 4;             // 0..124
        cp16(&dst[r * 136 + c4], src + (size_t)r * rstride + c4);
    }
}

// ---------------- GEMM1: exp(score) + fused rowsum/argmax (fp16 mma) --------------
__global__ void __launch_bounds__(256, 2) k_gemm1() {
    extern __shared__ uint32_t smem[];
    int tid  = threadIdx.x;
    int lane = tid & 31, warp = tid >> 5;
    int g = lane >> 2, tg = lane & 3;
    int wm = warp >> 2, wn = warp & 3;
    int i0 = blockIdx.y * 128;
    int j0 = blockIdx.x * 128;
    int b  = i0 >> 12, s0 = i0 & 4095;
    const uint32_t* Ag = g_xh + (size_t)b * (CDIM / 2) * HW + s0;
    const uint32_t* Bg = g_mhT + j0;

    float acc[4][4][4] = {};
    const int NIT = CDIM / 32;      // 16

    auto issue = [&](int it) {
        uint32_t* As = smem + (it % 3) * 4352;
        uint32_t* Bs = As + 2176;
        int r0 = it * 16;
        load_tile16(As, Ag + (size_t)r0 * HW,   HW,   tid);
        load_tile16(Bs, Bg + (size_t)r0 * KCOD, KCOD, tid);
        asm volatile("cp.async.commit_group;");
    };

    issue(0); issue(1);
    for (int it = 0; it < NIT; it++) {
        if (it + 1 < NIT) { asm volatile("cp.async.wait_group 1;"); }
        else              { asm volatile("cp.async.wait_group 0;"); }
        __syncthreads();
        if (it + 2 < NIT) issue(it + 2);
        const uint32_t* As = smem + (it % 3) * 4352;
        const uint32_t* Bs = As + 2176;
        #pragma unroll
        for (int kp = 0; kp < 16; kp += 8) {
            uint32_t af[4][4], bf[4][2];
            #pragma unroll
            for (int mt = 0; mt < 4; mt++) {
                int r = wm * 64 + mt * 16 + g;
                af[mt][0] = As[(kp + tg    ) * 136 + r    ];
                af[mt][1] = As[(kp + tg    ) * 136 + r + 8];
                af[mt][2] = As[(kp + tg + 4) * 136 + r    ];
                af[mt][3] = As[(kp + tg + 4) * 136 + r + 8];
            }
            #pragma unroll
            for (int nt = 0; nt < 4; nt++) {
                int c = wn * 32 + nt * 8 + g;
                bf[nt][0] = Bs[(kp + tg    ) * 136 + c];
                bf[nt][1] = Bs[(kp + tg + 4) * 136 + c];
            }
            #pragma unroll
            for (int mt = 0; mt < 4; mt++)
                #pragma unroll
                for (int nt = 0; nt < 4; nt++)
                    MMA_F16(acc[mt][nt], af[mt], bf[nt]);
        }
        __syncthreads();
    }

    int rbase = i0 + wm * 64;
    int cbase = j0 + wn * 32 + 2 * tg;
    float rm0[4], rm1[4];
    #pragma unroll
    for (int nt = 0; nt < 4; nt++) {
        rm0[nt] = g_rnm[cbase + nt * 8];
        rm1[nt] = g_rnm[cbase + nt * 8 + 1];
    }
    #pragma unroll
    for (int mt = 0; mt < 4; mt++) {
        int r0 = rbase + mt * 16 + g;
        int r1 = r0 + 8;
        float rx0 = g_rnx[r0], rx1 = g_rnx[r1];
        float sum0 = 0.f, sum1 = 0.f;
        float best0 = -2.f, best1 = -2.f;
        int bj0 = cbase, bj1 = cbase;
        #pragma unroll
        for (int nt = 0; nt < 4; nt++) {
            int c = cbase + nt * 8;
            float s00 = acc[mt][nt][0] * rx0 * rm0[nt];
            float s01 = acc[mt][nt][1] * rx0 * rm1[nt];
            float s10 = acc[mt][nt][2] * rx1 * rm0[nt];
            float s11 = acc[mt][nt][3] * rx1 * rm1[nt];
            float e00 = __expf(s00), e01 = __expf(s01);
            float e10 = __expf(s10), e11 = __expf(s11);
            size_t cp = (size_t)(c >> 1) * NTOK;
            g_expsH[cp + r0] = pack_h2(e00, e01);
            g_expsH[cp + r1] = pack_h2(e10, e11);
            sum0 += e00 + e01; sum1 += e10 + e11;
            if (s00 > best0) { best0 = s00; bj0 = c; }
            if (s01 > best0) { best0 = s01; bj0 = c + 1; }
            if (s10 > best1) { best1 = s10; bj1 = c; }
            if (s11 > best1) { best1 = s11; bj1 = c + 1; }
        }
        unsigned long long p0 = pack_max(best0, bj0);
        unsigned long long p1 = pack_max(best1, bj1);
        #pragma unroll
        for (int o = 1; o < 4; o <<= 1) {
            sum0 += __shfl_xor_sync(0xffffffffu, sum0, o);
            sum1 += __shfl_xor_sync(0xffffffffu, sum1, o);
            unsigned long long q0 = __shfl_xor_sync(0xffffffffu, p0, o);
            unsigned long long q1 = __shfl_xor_sync(0xffffffffu, p1, o);
            if (q0 > p0) p0 = q0;
            if (q1 > p1) p1 = q1;
        }
        if (tg == 0) {
            atomicAdd(&g_rowsum[r0], sum0);
            atomicAdd(&g_rowsum[r1], sum1);
            atomicMax(&g_amax[r0], p0);
            atomicMax(&g_amax[r1], p1);
        }
    }
}

// ---------------- scatter: half2 reads + red.v4 vector reductions ------------------
__global__ void k_scatter() {
    int i0 = blockIdx.x * 32;
    int b  = i0 >> 12, s0 = i0 & 4095;
    int tx = threadIdx.x, ty = threadIdx.y;   // 32 x 8
    __shared__ int sidx[32];
    int tid = ty * 32 + tx;
    if (tid < 32) {
        unsigned long long p = g_amax[i0 + tid];
        int idx = (int)(0xFFFFFFFFu - (unsigned)(p & 0xFFFFFFFFull));
        sidx[tid] = idx;
        atomicAdd(&g_cnt[idx], 1.0f);
    }
    __syncthreads();
    int idx = sidx[tx];
    const uint32_t* xb = g_xh + (size_t)b * (CDIM / 2) * HW + s0 + tx;
    float* erow = g_esum + (size_t)idx * CDIM;
    for (int q = ty; q < CDIM / 4; q += 8) {     // quad of channels 4q..4q+3
        uint32_t u0 = xb[(size_t)(2 * q)     * HW];
        uint32_t u1 = xb[(size_t)(2 * q + 1) * HW];
        __half2 h0 = *(__half2*)&u0;
        __half2 h1 = *(__half2*)&u1;
        float c0 = __low2float(h0), c1 = __high2float(h0);
        float c2 = __low2float(h1), c3 = __high2float(h1);
        asm volatile("red.global.add.v4.f32 [%0], {%1, %2, %3, %4};"
                     :: "l"(erow + 4 * q), "f"(c0), "f"(c1), "f"(c2), "f"(c3)
                     : "memory");
    }
}

// ---------------- EMA update -> half2 pairs along k -------------------------------
__global__ void k_update(const float* __restrict__ m) {
    int kp = blockIdx.x;            // k pair
    int k0 = 2 * kp, k1 = k0 + 1;
    float inv0 = 0.001f / (g_cnt[k0] + 1e-6f);
    float inv1 = 0.001f / (g_cnt[k1] + 1e-6f);
    for (int j = threadIdx.x; j < CDIM; j += blockDim.x) {
        float v0 = m[k0 * CDIM + j] * 0.999f + g_esum[k0 * CDIM + j] * inv0;
        float v1 = m[k1 * CDIM + j] * 0.999f + g_esum[k1 * CDIM + j] * inv1;
        g_newmH[(size_t)kp * CDIM + j] = pack_h2(v0, v1);
    }
}

// ---------------- GEMM2: out = (exps @ new_m) / rowsum (fp16 mma) ------------------
__global__ void __launch_bounds__(256, 2) k_gemm2(float* __restrict__ out) {
    extern __shared__ uint32_t smem[];
    int tid  = threadIdx.x;
    int lane = tid & 31, warp = tid >> 5;
    int g = lane >> 2, tg = lane & 3;
    int wm = warp >> 2, wn = warp & 3;
    int i0 = blockIdx.y * 128;   // tokens
    int j0 = blockIdx.x * 128;   // channels

    const uint32_t* Ag = g_expsH + i0;
    const uint32_t* Bg = g_newmH + j0;

    float acc[4][4][4] = {};
    const int NIT = KCOD / 32;           // 32

    auto issue = [&](int it) {
        uint32_t* As = smem + (it % 3) * 4352;
        uint32_t* Bs = As + 2176;
        int r0 = it * 16;
        load_tile16(As, Ag + (size_t)r0 * NTOK, NTOK, tid);
        load_tile16(Bs, Bg + (size_t)r0 * CDIM, CDIM, tid);
        asm volatile("cp.async.commit_group;");
    };

    issue(0); issue(1);
    for (int it = 0; it < NIT; it++) {
        if (it + 1 < NIT) { asm volatile("cp.async.wait_group 1;"); }
        else              { asm volatile("cp.async.wait_group 0;"); }
        __syncthreads();
        if (it + 2 < NIT) issue(it + 2);
        const uint32_t* As = smem + (it % 3) * 4352;
        const uint32_t* Bs = As + 2176;
        #pragma unroll
        for (int kp = 0; kp < 16; kp += 8) {
            uint32_t af[4][4], bf[4][2];
            #pragma unroll
            for (int mt = 0; mt < 4; mt++) {
                int r = wm * 64 + mt * 16 + g;
                af[mt][0] = As[(kp + tg    ) * 136 + r    ];
                af[mt][1] = As[(kp + tg    ) * 136 + r + 8];
                af[mt][2] = As[(kp + tg + 4) * 136 + r    ];
                af[mt][3] = As[(kp + tg + 4) * 136 + r + 8];
            }
            #pragma unroll
            for (int nt = 0; nt < 4; nt++) {
                int c = wn * 32 + nt * 8 + g;
                bf[nt][0] = Bs[(kp + tg    ) * 136 + c];
                bf[nt][1] = Bs[(kp + tg + 4) * 136 + c];
            }
            #pragma unroll
            for (int mt = 0; mt < 4; mt++)
                #pragma unroll
                for (int nt = 0; nt < 4; nt++)
                    MMA_F16(acc[mt][nt], af[mt], bf[nt]);
        }
        __syncthreads();
    }

    int b = i0 >> 12;
    int rbase = i0 + wm * 64;
    int cbase = j0 + wn * 32 + 2 * tg;
    #pragma unroll
    for (int mt = 0; mt < 4; mt++) {
        int r0 = rbase + mt * 16 + g;
        int r1 = r0 + 8;
        float ri0 = 1.0f / g_rowsum[r0];
        float ri1 = 1.0f / g_rowsum[r1];
        int sA = r0 & 4095, sB = r1 & 4095;
        #pragma unroll
        for (int nt = 0; nt < 4; nt++) {
            int c = cbase + nt * 8;
            out[(size_t)(b * CDIM + c    ) * HW + sA] = acc[mt][nt][0] * ri0;
            out[(size_t)(b * CDIM + c + 1) * HW + sA] = acc[mt][nt][1] * ri0;
            out[(size_t)(b * CDIM + c    ) * HW + sB] = acc[mt][nt][2] * ri1;
            out[(size_t)(b * CDIM + c + 1) * HW + sB] = acc[mt][nt][3] * ri1;
        }
    }
}

// ---------------- launch -------------------------------------------------------------
extern "C" void kernel_launch(void* const* d_in, const int* in_sizes, int n_in,
                              void* d_out, int out_size) {
    const float* x = (const float*)d_in[0];
    const float* m = (const float*)d_in[1];
    float* out = (float*)d_out;

    const int SMEM = 3 * 4352 * 4;   // 52224 B
    cudaFuncSetAttribute(k_gemm1, cudaFuncAttributeMaxDynamicSharedMemorySize, SMEM);
    cudaFuncSetAttribute(k_gemm2, cudaFuncAttributeMaxDynamicSharedMemorySize, SMEM);

    k_zero<<<256, 256>>>();
    k_norm_pack<<<NTOK / 32, dim3(32, 8)>>>(x);
    k_prep_m<<<KCOD, 256>>>(m);
    k_gemm1<<<dim3(KCOD / 128, NTOK / 128), 256, SMEM>>>();
    k_scatter<<<NTOK / 32, dim3(32, 8)>>>();
    k_update<<<KCOD / 2, 256>>>(m);
    k_gemm2<<<dim3(CDIM / 128, NTOK / 128), 256, SMEM>>>(out);
}